// round 4
// baseline (speedup 1.0000x reference)
#include <cuda_runtime.h>
#include <math.h>
#include <stdint.h>

// ---------------- problem constants ----------------
#define BATCH   32
#define REPD    1024
#define NVERB   504
#define NROLE   190
#define NNOUN   11538
#define MRMAX   6
#define HIDE    32
#define NHEAD   4
#define HDIM    8
#define MAXN    512
#define ROWS    6080            // NROLE * BATCH

// output offsets (float32 concat of the returned tuple)
#define O_REP   0
#define O_VPOT  32768           // 32*1024
#define O_RN    48896           // +32*504
#define O_NORM  70199936        // +6080*11538
#define O_VMAX  70199968        // +32
#define O_MAXI  70216096        // +32*504
// total 70312864

// ---------------- scratch (device globals; no allocation allowed) ----------------
__device__ float g_node[ROWS * HIDE];     // node, layout [l][b][h] == row-major (6080,32), row = l*32+b
__device__ float g_qkv[ROWS * 96];        // qkv per layer
__device__ float g_ao[ROWS * HIDE];       // attention output (pre out-proj)
__device__ float g_marg[ROWS];            // rn_marginal[r*32+b]
__device__ float g_rmax[ROWS];            // r_max[r*32+b]
__device__ int   g_rmaxi[ROWS];           // r_maxi[r*32+b]

// ---------------- f32x2 helpers (packed fp32 pipe, sm_100+) ----------------
__device__ __forceinline__ unsigned long long pack2(float lo, float hi) {
    unsigned long long r;
    asm("mov.b64 %0, {%1, %2};" : "=l"(r) : "r"(__float_as_uint(lo)), "r"(__float_as_uint(hi)));
    return r;
}
__device__ __forceinline__ void unpack2(unsigned long long p, float& lo, float& hi) {
    unsigned int a, b;
    asm("mov.b64 {%0, %1}, %2;" : "=r"(a), "=r"(b) : "l"(p));
    lo = __uint_as_float(a); hi = __uint_as_float(b);
}
__device__ __forceinline__ unsigned long long ffma2(unsigned long long a, unsigned long long b,
                                                    unsigned long long c) {
    unsigned long long d;
    asm("fma.rn.f32x2 %0, %1, %2, %3;" : "=l"(d) : "l"(a), "l"(b), "l"(c));
    return d;
}

// ============================================================================
// K1/K2: C(32xN) = rep(32x1024) @ B(1024xN) + bias
// BM=16 (grid.y=2), BN=64, 256 threads, 2x2 outputs/thread.
// mode 0: plain store to Cout[row*N+col]
// mode 1: node store g_node[(col/32)*1024 + row*32 + (col%32)]
// ============================================================================
__global__ __launch_bounds__(256) void gemm_rep_kernel(
    const float* __restrict__ A, const float* __restrict__ Bm,
    const float* __restrict__ bias, float* __restrict__ Cout, int N, int mode)
{
    __shared__ float As[16][33];
    __shared__ float Bs[32][64];
    const int tid = threadIdx.x;
    const int tx = tid & 31, ty = tid >> 5;
    const int n0 = blockIdx.x * 64;
    const int m0 = blockIdx.y * 16;

    float acc00 = 0.f, acc01 = 0.f, acc10 = 0.f, acc11 = 0.f;

    for (int k0 = 0; k0 < REPD; k0 += 32) {
        // load A tile (16 x 32)
        {
            int m  = tid >> 4;          // 0..15
            int kk = (tid & 15) * 2;    // 0..30
            float2 v = *(const float2*)(A + (m0 + m) * REPD + k0 + kk);
            As[m][kk] = v.x; As[m][kk + 1] = v.y;
        }
        // load B tile (32 x 64)
#pragma unroll
        for (int it = 0; it < 8; it++) {
            int idx = tid + it * 256;
            int kk = idx >> 6, cc = idx & 63;
            int col = n0 + cc;
            Bs[kk][cc] = (col < N) ? Bm[(size_t)(k0 + kk) * N + col] : 0.f;
        }
        __syncthreads();
#pragma unroll
        for (int kk = 0; kk < 32; kk++) {
            float a0 = As[ty * 2 + 0][kk];
            float a1 = As[ty * 2 + 1][kk];
            float b0 = Bs[kk][tx];
            float b1 = Bs[kk][tx + 32];
            acc00 += a0 * b0; acc01 += a0 * b1;
            acc10 += a1 * b0; acc11 += a1 * b1;
        }
        __syncthreads();
    }

    float accs[2][2] = {{acc00, acc01}, {acc10, acc11}};
#pragma unroll
    for (int r = 0; r < 2; r++) {
#pragma unroll
        for (int c = 0; c < 2; c++) {
            int row = m0 + ty * 2 + r;
            int col = n0 + tx + 32 * c;
            if (col < N) {
                float v = accs[r][c] + bias[col];
                if (mode == 0) {
                    Cout[(size_t)row * N + col] = v;
                } else {
                    g_node[(size_t)(col >> 5) * (BATCH * HIDE) + row * HIDE + (col & 31)] = v;
                }
            }
        }
    }
}

// ============================================================================
// MHA stage kernels
// ============================================================================
// qkv[row][c] = in_b[i][c] + sum_e node[row][e] * in_w[i][c][e]
__global__ __launch_bounds__(256) void qkv_kernel(
    const float* __restrict__ inw, const float* __restrict__ inb, int layer)
{
    int o = blockIdx.x * 256 + threadIdx.x;       // exact: ROWS*96 = 2280*256
    int row = o / 96, c = o % 96;
    const float4* xv = (const float4*)(g_node + (size_t)row * HIDE);
    const float4* wv = (const float4*)(inw + (size_t)layer * 96 * HIDE + c * HIDE);
    float acc = inb[layer * 96 + c];
#pragma unroll
    for (int q = 0; q < 8; q++) {
        float4 x = xv[q], w = wv[q];
        acc += x.x * w.x + x.y * w.y + x.z * w.z + x.w * w.w;
    }
    g_qkv[(size_t)row * 96 + c] = acc;
}

// one block per (head, batch); online softmax over 190 keys
__global__ __launch_bounds__(192) void attn_kernel()
{
    const int h = blockIdx.x, b = blockIdx.y;
    __shared__ float ks[NROLE][HDIM];
    __shared__ float vs[NROLE][HDIM];
    const int tid = threadIdx.x;

    for (int e = tid; e < NROLE * HDIM; e += 192) {
        int m = e >> 3, d = e & 7;
        size_t base = (size_t)(m * BATCH + b) * 96 + h * HDIM + d;
        ks[m][d] = g_qkv[base + 32];
        vs[m][d] = g_qkv[base + 64];
    }
    __syncthreads();

    const int l = tid;
    if (l < NROLE) {
        float q[8];
        const float4* qv = (const float4*)(g_qkv + (size_t)(l * BATCH + b) * 96 + h * HDIM);
        float4 q0 = qv[0], q1 = qv[1];
        q[0] = q0.x; q[1] = q0.y; q[2] = q0.z; q[3] = q0.w;
        q[4] = q1.x; q[5] = q1.y; q[6] = q1.z; q[7] = q1.w;
        const float scale = 0.3535533905932738f;   // 1/sqrt(8)

        float rm = -1e30f, rs = 0.f;
        float racc[8] = {0.f, 0.f, 0.f, 0.f, 0.f, 0.f, 0.f, 0.f};
        for (int m = 0; m < NROLE; m++) {
            float s = 0.f;
#pragma unroll
            for (int d = 0; d < 8; d++) s += q[d] * ks[m][d];
            s *= scale;
            float nm = fmaxf(rm, s);
            float f = __expf(rm - nm);
            float p = __expf(s - nm);
            rs = rs * f + p;
#pragma unroll
            for (int d = 0; d < 8; d++) racc[d] = racc[d] * f + p * vs[m][d];
            rm = nm;
        }
        float inv = 1.f / rs;
        float* op = g_ao + (size_t)(l * BATCH + b) * HIDE + h * HDIM;
#pragma unroll
        for (int d = 0; d < 8; d++) op[d] = racc[d] * inv;
    }
}

// node[row][e] = out_b[i][e] + sum_j ao[row][j] * out_w[i][e][j]
__global__ __launch_bounds__(256) void proj_kernel(
    const float* __restrict__ ow, const float* __restrict__ ob, int layer)
{
    int o = blockIdx.x * 256 + threadIdx.x;       // exact: ROWS*32 = 760*256
    int row = o >> 5, e = o & 31;
    const float4* av = (const float4*)(g_ao + (size_t)row * HIDE);
    const float4* wv = (const float4*)(ow + (size_t)layer * HIDE * HIDE + e * HIDE);
    float acc = ob[layer * HIDE + e];
#pragma unroll
    for (int q = 0; q < 8; q++) {
        float4 x = av[q], w = wv[q];
        acc += x.x * w.x + x.y * w.y + x.z * w.z + x.w * w.w;
    }
    g_node[(size_t)row * HIDE + e] = acc;
}

// ============================================================================
// K3: rn = node(6080x32) @ W_n(32x11538) + b_n   (the big one, f32x2 FMA)
// BM=128, BN=128, 256 threads (16x16), each thread 8 rows x 4 float2-cols.
// ============================================================================
__global__ __launch_bounds__(256) void gemm_big_kernel(
    const float* __restrict__ Wn, const float* __restrict__ bn, float* __restrict__ Crn)
{
    __shared__ float Ast[32 * 132];   // [k][m], padded stride 132 (16B aligned rows)
    __shared__ float Bs[32 * 128];    // [k][n]
    __shared__ float bns[128];

    const int tid = threadIdx.x;
    const int tx = tid & 15, ty = tid >> 4;
    const int n0 = blockIdx.x * 128;
    const int m0 = blockIdx.y * 128;

    // fill Ast (transposed) via float4 loads from g_node
#pragma unroll
    for (int it = 0; it < 4; it++) {
        int q = tid + it * 256;            // float4 id 0..1023
        int r = q >> 3, k4 = (q & 7) * 4;
        float4 v = make_float4(0.f, 0.f, 0.f, 0.f);
        if (m0 + r < ROWS) v = *(const float4*)(g_node + (size_t)(m0 + r) * HIDE + k4);
        Ast[(k4 + 0) * 132 + r] = v.x;
        Ast[(k4 + 1) * 132 + r] = v.y;
        Ast[(k4 + 2) * 132 + r] = v.z;
        Ast[(k4 + 3) * 132 + r] = v.w;
    }
    // fill Bs via float2 loads (W_n rows are only 8B-aligned for odd k)
#pragma unroll
    for (int it = 0; it < 8; it++) {
        int q = tid + it * 256;            // float2 id 0..2047
        int kk = q >> 6, c2 = (q & 63) * 2;
        int col = n0 + c2;
        float2 v = make_float2(0.f, 0.f);
        if (col < NNOUN) v = *(const float2*)(Wn + (size_t)kk * NNOUN + col);
        *(float2*)&Bs[kk * 128 + c2] = v;
    }
    if (tid < 128) bns[tid] = (n0 + tid < NNOUN) ? bn[n0 + tid] : 0.f;
    __syncthreads();

    unsigned long long acc[8][4];
#pragma unroll
    for (int i = 0; i < 8; i++)
#pragma unroll
        for (int j = 0; j < 4; j++) acc[i][j] = 0ull;

#pragma unroll 4
    for (int k = 0; k < 32; k++) {
        const float* ar = Ast + k * 132 + ty * 8;
        float4 a0 = *(const float4*)(ar);
        float4 a1 = *(const float4*)(ar + 4);
        unsigned long long ap[8];
        ap[0] = pack2(a0.x, a0.x); ap[1] = pack2(a0.y, a0.y);
        ap[2] = pack2(a0.z, a0.z); ap[3] = pack2(a0.w, a0.w);
        ap[4] = pack2(a1.x, a1.x); ap[5] = pack2(a1.y, a1.y);
        ap[6] = pack2(a1.z, a1.z); ap[7] = pack2(a1.w, a1.w);
        const float* br = Bs + k * 128 + 2 * tx;
        unsigned long long bp[4];
#pragma unroll
        for (int j = 0; j < 4; j++) bp[j] = *(const unsigned long long*)(br + 32 * j);
#pragma unroll
        for (int i = 0; i < 8; i++)
#pragma unroll
            for (int j = 0; j < 4; j++)
                acc[i][j] = ffma2(ap[i], bp[j], acc[i][j]);
    }

#pragma unroll
    for (int i = 0; i < 8; i++) {
        int m = m0 + ty * 8 + i;
        if (m < ROWS) {
            float* crow = Crn + (size_t)m * NNOUN;
#pragma unroll
            for (int j = 0; j < 4; j++) {
                int col = n0 + 2 * tx + 32 * j;
                if (col < NNOUN) {
                    float lo, hi; unpack2(acc[i][j], lo, hi);
                    float2 bb = *(const float2*)&bns[2 * tx + 32 * j];
                    float2 ov = make_float2(lo + bb.x, hi + bb.y);
                    *(float2*)(crow + col) = ov;
                }
            }
        }
    }
}

// ============================================================================
// K4: grouped max / first-argmax / logsumexp per (role, batch)
// one block per role; warp w handles batches w*4 .. w*4+3
// ============================================================================
__global__ __launch_bounds__(256) void group_kernel(
    const float* __restrict__ rn, const int* __restrict__ rnidx)
{
    const int r = blockIdx.x;
    __shared__ int   sidx[MAXN];
    __shared__ float svals[8][MAXN];
    const int tid = threadIdx.x;
    sidx[tid]       = rnidx[(size_t)r * MAXN + tid];
    sidx[tid + 256] = rnidx[(size_t)r * MAXN + tid + 256];
    __syncthreads();

    const int w = tid >> 5, lane = tid & 31;
    for (int q = 0; q < 4; q++) {
        const int b = w * 4 + q;
        const float* row = rn + (size_t)(r * BATCH + b) * NNOUN;
        float lm = -1e30f; int li = 1 << 30;
        for (int j = lane; j < MAXN; j += 32) {
            float v = row[sidx[j]];
            svals[w][j] = v;
            if (v > lm || (v == lm && j < li)) { lm = v; li = j; }
        }
#pragma unroll
        for (int off = 16; off; off >>= 1) {
            float ov = __shfl_down_sync(0xffffffffu, lm, off);
            int   oi = __shfl_down_sync(0xffffffffu, li, off);
            if (ov > lm || (ov == lm && oi < li)) { lm = ov; li = oi; }
        }
        lm = __shfl_sync(0xffffffffu, lm, 0);
        li = __shfl_sync(0xffffffffu, li, 0);

        float ls = 0.f;
        for (int j = lane; j < MAXN; j += 32) ls += __expf(svals[w][j] - lm);
#pragma unroll
        for (int off = 16; off; off >>= 1) ls += __shfl_down_sync(0xffffffffu, ls, off);

        if (lane == 0) {
            int o = r * BATCH + b;
            g_rmax[o]  = lm;
            g_marg[o]  = lm + logf(ls);
            g_rmaxi[o] = sidx[li];
        }
    }
}

// ============================================================================
// K5: per-batch epilogue — v_marginal, norm (logsumexp over 504), v_max, vr_maxi_g
// ============================================================================
__global__ __launch_bounds__(256) void final_kernel(
    const int* __restrict__ pad, float* __restrict__ out)
{
    const int b = blockIdx.x;
    __shared__ float mc[NROLE + 1];
    __shared__ float xc[NROLE + 1];
    __shared__ int   ic[NROLE + 1];
    __shared__ float vmarg[NVERB];
    __shared__ float red[256];
    const int tid = threadIdx.x;

    if (tid == 0) { mc[0] = 0.f; xc[0] = 0.f; ic[0] = 0; }
    for (int j = tid; j < NROLE; j += 256) {
        mc[j + 1] = g_marg[j * BATCH + b];
        xc[j + 1] = g_rmax[j * BATCH + b];
        ic[j + 1] = g_rmaxi[j * BATCH + b];
    }
    __syncthreads();

    const float* vpot = out + O_VPOT + (size_t)b * NVERB;
    for (int v = tid; v < NVERB; v += 256) {
        float sm = 0.f, sx = 0.f;
#pragma unroll
        for (int s = 0; s < MRMAX; s++) {
            int p = pad[v * MRMAX + s];
            sm += mc[p]; sx += xc[p];
            out[O_MAXI + ((size_t)b * NVERB + v) * MRMAX + s] = (float)ic[p];
        }
        float vp = vpot[v];
        vmarg[v] = sm + vp;
        out[O_VMAX + (size_t)b * NVERB + v] = sx + vp;
    }
    __syncthreads();

    float lm = -1e30f;
    for (int v = tid; v < NVERB; v += 256) lm = fmaxf(lm, vmarg[v]);
    red[tid] = lm; __syncthreads();
    for (int s = 128; s; s >>= 1) { if (tid < s) red[tid] = fmaxf(red[tid], red[tid + s]); __syncthreads(); }
    float gm = red[0]; __syncthreads();

    float ls = 0.f;
    for (int v = tid; v < NVERB; v += 256) ls += __expf(vmarg[v] - gm);
    red[tid] = ls; __syncthreads();
    for (int s = 128; s; s >>= 1) { if (tid < s) red[tid] += red[tid + s]; __syncthreads(); }
    if (tid == 0) out[O_NORM + b] = gm + logf(red[0]);
}

// ============================================================================
// launch
// ============================================================================
extern "C" void kernel_launch(void* const* d_in, const int* in_sizes, int n_in,
                              void* d_out, int out_size)
{
    const float* rep  = (const float*)d_in[0];
    const float* W_v  = (const float*)d_in[1];
    const float* b_v  = (const float*)d_in[2];
    const float* W_r  = (const float*)d_in[3];
    const float* b_r  = (const float*)d_in[4];
    const float* inw  = (const float*)d_in[5];
    const float* inb  = (const float*)d_in[6];
    const float* ow   = (const float*)d_in[7];
    const float* ob   = (const float*)d_in[8];
    const float* W_n  = (const float*)d_in[9];
    const float* b_n  = (const float*)d_in[10];
    const int*   ridx = (const int*)d_in[11];
    const int*   pad  = (const int*)d_in[12];
    float* out = (float*)d_out;

    // rep passthrough
    cudaMemcpyAsync(out + O_REP, rep, (size_t)BATCH * REPD * sizeof(float),
                    cudaMemcpyDeviceToDevice);

    // v_potential and node0
    gemm_rep_kernel<<<dim3(8, 2), 256>>>(rep, W_v, b_v, out + O_VPOT, NVERB, 0);
    gemm_rep_kernel<<<dim3(95, 2), 256>>>(rep, W_r, b_r, nullptr, NROLE * HIDE, 1);

    // 3 MHA layers
    for (int i = 0; i < 3; i++) {
        qkv_kernel<<<2280, 256>>>(inw, inb, i);
        attn_kernel<<<dim3(NHEAD, BATCH), 192>>>();
        proj_kernel<<<760, 256>>>(ow, ob, i);
    }

    // rn_potential (big GEMM) straight into the output buffer
    gemm_big_kernel<<<dim3(91, 48), 256>>>(W_n, b_n, out + O_RN);

    // grouped max/argmax/logsumexp
    group_kernel<<<NROLE, 256>>>(out + O_RN, ridx);

    // final per-batch epilogue
    final_kernel<<<BATCH, 256>>>(pad, out);
}

// round 5
// speedup vs baseline: 1.0829x; 1.0829x over previous
#include <cuda_runtime.h>
#include <math.h>
#include <stdint.h>

// ---------------- problem constants ----------------
#define BATCH   32
#define REPD    1024
#define NVERB   504
#define NROLE   190
#define NNOUN   11538
#define MRMAX   6
#define HIDE    32
#define NHEAD   4
#define HDIM    8
#define MAXN    512
#define ROWS    6080            // NROLE * BATCH

// output offsets (float32 concat of the returned tuple)
#define O_REP   0
#define O_VPOT  32768           // 32*1024
#define O_RN    48896           // +32*504
#define O_NORM  70199936        // +6080*11538
#define O_VMAX  70199968        // +32
#define O_MAXI  70216096        // +32*504
// total 70312864

// ---------------- scratch (device globals; no allocation allowed) ----------------
__device__ float g_node[ROWS * HIDE];     // node, row = l*32+b
__device__ float g_ao[ROWS * HIDE];       // attention output (pre out-proj)
__device__ float g_marg[ROWS];            // rn_marginal[r*32+b]
__device__ float g_rmax[ROWS];            // r_max[r*32+b]
__device__ int   g_rmaxi[ROWS];           // r_maxi[r*32+b]

// ---------------- f32x2 helpers (packed fp32 pipe, sm_100+) ----------------
__device__ __forceinline__ unsigned long long pack2(float lo, float hi) {
    unsigned long long r;
    asm("mov.b64 %0, {%1, %2};" : "=l"(r) : "r"(__float_as_uint(lo)), "r"(__float_as_uint(hi)));
    return r;
}
__device__ __forceinline__ void unpack2(unsigned long long p, float& lo, float& hi) {
    unsigned int a, b;
    asm("mov.b64 {%0, %1}, %2;" : "=r"(a), "=r"(b) : "l"(p));
    lo = __uint_as_float(a); hi = __uint_as_float(b);
}
__device__ __forceinline__ unsigned long long ffma2(unsigned long long a, unsigned long long b,
                                                    unsigned long long c) {
    unsigned long long d;
    asm("fma.rn.f32x2 %0, %1, %2, %3;" : "=l"(d) : "l"(a), "l"(b), "l"(c));
    return d;
}

// ============================================================================
// K1/K2: C(32xN) = rep(32x1024) @ B(1024xN) + bias
// ============================================================================
__global__ __launch_bounds__(256) void gemm_rep_kernel(
    const float* __restrict__ A, const float* __restrict__ Bm,
    const float* __restrict__ bias, float* __restrict__ Cout, int N, int mode)
{
    __shared__ float As[16][33];
    __shared__ float Bs[32][64];
    const int tid = threadIdx.x;
    const int tx = tid & 31, ty = tid >> 5;
    const int n0 = blockIdx.x * 64;
    const int m0 = blockIdx.y * 16;

    float acc00 = 0.f, acc01 = 0.f, acc10 = 0.f, acc11 = 0.f;

    for (int k0 = 0; k0 < REPD; k0 += 32) {
        {
            int m  = tid >> 4;
            int kk = (tid & 15) * 2;
            float2 v = *(const float2*)(A + (m0 + m) * REPD + k0 + kk);
            As[m][kk] = v.x; As[m][kk + 1] = v.y;
        }
#pragma unroll
        for (int it = 0; it < 8; it++) {
            int idx = tid + it * 256;
            int kk = idx >> 6, cc = idx & 63;
            int col = n0 + cc;
            Bs[kk][cc] = (col < N) ? Bm[(size_t)(k0 + kk) * N + col] : 0.f;
        }
        __syncthreads();
#pragma unroll
        for (int kk = 0; kk < 32; kk++) {
            float a0 = As[ty * 2 + 0][kk];
            float a1 = As[ty * 2 + 1][kk];
            float b0 = Bs[kk][tx];
            float b1 = Bs[kk][tx + 32];
            acc00 += a0 * b0; acc01 += a0 * b1;
            acc10 += a1 * b0; acc11 += a1 * b1;
        }
        __syncthreads();
    }

    float accs[2][2] = {{acc00, acc01}, {acc10, acc11}};
#pragma unroll
    for (int r = 0; r < 2; r++) {
#pragma unroll
        for (int c = 0; c < 2; c++) {
            int row = m0 + ty * 2 + r;
            int col = n0 + tx + 32 * c;
            if (col < N) {
                float v = accs[r][c] + bias[col];
                if (mode == 0) {
                    Cout[(size_t)row * N + col] = v;
                } else {
                    g_node[(size_t)(col >> 5) * (BATCH * HIDE) + row * HIDE + (col & 31)] = v;
                }
            }
        }
    }
}

// ============================================================================
// attn: fused qkv + two-pass softmax + AV for one (head, batch)
// grid (4, 32), 192 threads
// ============================================================================
__global__ __launch_bounds__(192) void attn_kernel(
    const float* __restrict__ inw, const float* __restrict__ inb, int layer)
{
    const int h = blockIdx.x, b = blockIdx.y;
    __shared__ __align__(16) float xs[NROLE][HIDE];   // node rows for this batch
    __shared__ __align__(16) float ks[NROLE][HDIM];
    __shared__ __align__(16) float vs[NROLE][HDIM];
    __shared__ __align__(16) float wsh[24][HIDE];     // rows 0..7 q, 8..15 k, 16..23 v
    __shared__ float bsh[24];
    const int tid = threadIdx.x;

    for (int e = tid; e < NROLE * HIDE; e += 192) {
        int m = e >> 5, d = e & 31;
        xs[m][d] = g_node[(size_t)(m * BATCH + b) * HIDE + d];
    }
    for (int e = tid; e < 24 * HIDE; e += 192) {
        int rr = e >> 5, d = e & 31;
        int grow = (rr >> 3) * HIDE + h * HDIM + (rr & 7);
        wsh[rr][d] = inw[((size_t)layer * 96 + grow) * HIDE + d];
    }
    if (tid < 24) {
        int grow = (tid >> 3) * HIDE + h * HDIM + (tid & 7);
        bsh[tid] = inb[layer * 96 + grow];
    }
    __syncthreads();

    // compute k, v into smem (190*16 outputs)
    for (int o = tid; o < NROLE * 16; o += 192) {
        int m = o >> 4, c = o & 15;
        int wr = 8 + c;                 // c<8 -> k row, c>=8 -> v row
        const unsigned long long* xp = (const unsigned long long*)xs[m];
        const unsigned long long* wp = (const unsigned long long*)wsh[wr];
        unsigned long long acc = 0ull;
#pragma unroll
        for (int i = 0; i < 16; i++) acc = ffma2(xp[i], wp[i], acc);
        float lo, hi; unpack2(acc, lo, hi);
        float val = lo + hi + bsh[wr];
        if (c < 8) ks[m][c] = val; else vs[m][c - 8] = val;
    }
    __syncthreads();

    const int l = tid;
    if (l < NROLE) {
        // q for this l
        unsigned long long qp[4];
        {
            const unsigned long long* xp = (const unsigned long long*)xs[l];
            float qv[8];
#pragma unroll
            for (int d = 0; d < 8; d++) {
                const unsigned long long* wp = (const unsigned long long*)wsh[d];
                unsigned long long acc = 0ull;
#pragma unroll
                for (int i = 0; i < 16; i++) acc = ffma2(xp[i], wp[i], acc);
                float lo, hi; unpack2(acc, lo, hi);
                qv[d] = lo + hi + bsh[d];
            }
#pragma unroll
            for (int i = 0; i < 4; i++) qp[i] = pack2(qv[2 * i], qv[2 * i + 1]);
        }
        const float scale = 0.3535533905932738f;   // 1/sqrt(8)

        // pass 1: running max (no exp -> no serial MUFU chain)
        float mx = -1e30f;
        for (int m = 0; m < NROLE; m++) {
            const unsigned long long* kr = (const unsigned long long*)ks[m];
            unsigned long long acc = 0ull;
#pragma unroll
            for (int i = 0; i < 4; i++) acc = ffma2(qp[i], kr[i], acc);
            float lo, hi; unpack2(acc, lo, hi);
            mx = fmaxf(mx, (lo + hi) * scale);
        }
        // pass 2: independent exps + AV accumulation
        float ssum = 0.f;
        unsigned long long racc[4] = {0ull, 0ull, 0ull, 0ull};
        for (int m = 0; m < NROLE; m++) {
            const unsigned long long* kr = (const unsigned long long*)ks[m];
            unsigned long long acc = 0ull;
#pragma unroll
            for (int i = 0; i < 4; i++) acc = ffma2(qp[i], kr[i], acc);
            float lo, hi; unpack2(acc, lo, hi);
            float p = __expf((lo + hi) * scale - mx);
            ssum += p;
            unsigned long long pp = pack2(p, p);
            const unsigned long long* vr = (const unsigned long long*)vs[m];
#pragma unroll
            for (int i = 0; i < 4; i++) racc[i] = ffma2(pp, vr[i], racc[i]);
        }
        float inv = 1.f / ssum;
        float* op = g_ao + (size_t)(l * BATCH + b) * HIDE + h * HDIM;
        float4 o0, o1; float lo, hi;
        unpack2(racc[0], lo, hi); o0.x = lo * inv; o0.y = hi * inv;
        unpack2(racc[1], lo, hi); o0.z = lo * inv; o0.w = hi * inv;
        unpack2(racc[2], lo, hi); o1.x = lo * inv; o1.y = hi * inv;
        unpack2(racc[3], lo, hi); o1.z = lo * inv; o1.w = hi * inv;
        *(float4*)op = o0; *(float4*)(op + 4) = o1;
    }
}

// node[row][e] = out_b[i][e] + sum_j ao[row][j] * out_w[i][e][j]
__global__ __launch_bounds__(256) void proj_kernel(
    const float* __restrict__ ow, const float* __restrict__ ob, int layer)
{
    int o = blockIdx.x * 256 + threadIdx.x;       // exact: ROWS*32 = 760*256
    int row = o >> 5, e = o & 31;
    const float4* av = (const float4*)(g_ao + (size_t)row * HIDE);
    const float4* wv = (const float4*)(ow + (size_t)layer * HIDE * HIDE + e * HIDE);
    float acc = ob[layer * HIDE + e];
#pragma unroll
    for (int q = 0; q < 8; q++) {
        float4 x = av[q], w = wv[q];
        acc += x.x * w.x + x.y * w.y + x.z * w.z + x.w * w.w;
    }
    g_node[(size_t)row * HIDE + e] = acc;
}

// ============================================================================
// K3: rn = node(6080x32) @ W_n(32x11538) + b_n   (f32x2 FMA)
// ============================================================================
__global__ __launch_bounds__(256) void gemm_big_kernel(
    const float* __restrict__ Wn, const float* __restrict__ bn, float* __restrict__ Crn)
{
    __shared__ float Ast[32 * 132];   // [k][m], padded
    __shared__ float Bs[32 * 128];    // [k][n]
    __shared__ float bns[128];

    const int tid = threadIdx.x;
    const int tx = tid & 15, ty = tid >> 4;
    const int n0 = blockIdx.x * 128;
    const int m0 = blockIdx.y * 128;

#pragma unroll
    for (int it = 0; it < 4; it++) {
        int q = tid + it * 256;
        int r = q >> 3, k4 = (q & 7) * 4;
        float4 v = make_float4(0.f, 0.f, 0.f, 0.f);
        if (m0 + r < ROWS) v = *(const float4*)(g_node + (size_t)(m0 + r) * HIDE + k4);
        Ast[(k4 + 0) * 132 + r] = v.x;
        Ast[(k4 + 1) * 132 + r] = v.y;
        Ast[(k4 + 2) * 132 + r] = v.z;
        Ast[(k4 + 3) * 132 + r] = v.w;
    }
#pragma unroll
    for (int it = 0; it < 8; it++) {
        int q = tid + it * 256;
        int kk = q >> 6, c2 = (q & 63) * 2;
        int col = n0 + c2;
        float2 v = make_float2(0.f, 0.f);
        if (col < NNOUN) v = *(const float2*)(Wn + (size_t)kk * NNOUN + col);
        *(float2*)&Bs[kk * 128 + c2] = v;
    }
    if (tid < 128) bns[tid] = (n0 + tid < NNOUN) ? bn[n0 + tid] : 0.f;
    __syncthreads();

    unsigned long long acc[8][4];
#pragma unroll
    for (int i = 0; i < 8; i++)
#pragma unroll
        for (int j = 0; j < 4; j++) acc[i][j] = 0ull;

#pragma unroll 4
    for (int k = 0; k < 32; k++) {
        const float* ar = Ast + k * 132 + ty * 8;
        float4 a0 = *(const float4*)(ar);
        float4 a1 = *(const float4*)(ar + 4);
        unsigned long long ap[8];
        ap[0] = pack2(a0.x, a0.x); ap[1] = pack2(a0.y, a0.y);
        ap[2] = pack2(a0.z, a0.z); ap[3] = pack2(a0.w, a0.w);
        ap[4] = pack2(a1.x, a1.x); ap[5] = pack2(a1.y, a1.y);
        ap[6] = pack2(a1.z, a1.z); ap[7] = pack2(a1.w, a1.w);
        const float* br = Bs + k * 128 + 2 * tx;
        unsigned long long bp[4];
#pragma unroll
        for (int j = 0; j < 4; j++) bp[j] = *(const unsigned long long*)(br + 32 * j);
#pragma unroll
        for (int i = 0; i < 8; i++)
#pragma unroll
            for (int j = 0; j < 4; j++)
                acc[i][j] = ffma2(ap[i], bp[j], acc[i][j]);
    }

#pragma unroll
    for (int i = 0; i < 8; i++) {
        int m = m0 + ty * 8 + i;
        if (m < ROWS) {
            float* crow = Crn + (size_t)m * NNOUN;
#pragma unroll
            for (int j = 0; j < 4; j++) {
                int col = n0 + 2 * tx + 32 * j;
                if (col < NNOUN) {
                    float lo, hi; unpack2(acc[i][j], lo, hi);
                    float2 bb = *(const float2*)&bns[2 * tx + 32 * j];
                    *(float2*)(crow + col) = make_float2(lo + bb.x, hi + bb.y);
                }
            }
        }
    }
}

// ============================================================================
// K4: grouped max / first-argmax / logsumexp per (role, batch) — RECOMPUTED
// from node @ gathered W_n columns (never touches the 280MB rn buffer).
// one block per role, dynamic smem 72KB.
// ============================================================================
__global__ __launch_bounds__(256) void group_kernel(
    const float* __restrict__ Wn, const float* __restrict__ bn, const int* __restrict__ rnidx)
{
    extern __shared__ __align__(16) float gsm[];
    unsigned long long* Wg8 = (unsigned long long*)gsm;   // [16][512] f32x2 pairs (64KB)
    float* nsh = gsm + 16384;                             // [32][32] node rows
    float* bg  = gsm + 17408;                             // [512] gathered bias
    int*  sidx = (int*)(gsm + 17920);                     // [512]
    const int r = blockIdx.x, tid = threadIdx.x;

    sidx[tid]       = rnidx[(size_t)r * MAXN + tid];
    sidx[tid + 256] = rnidx[(size_t)r * MAXN + tid + 256];
    for (int e = tid; e < 1024; e += 256) nsh[e] = g_node[(size_t)r * 1024 + e];
    __syncthreads();
    for (int e = tid; e < 512; e += 256) bg[e] = bn[sidx[e]];
    for (int e = tid; e < 8192; e += 256) {
        int dd = e >> 9, j = e & 511;
        int c = sidx[j];
        Wg8[e] = pack2(Wn[(size_t)(2 * dd) * NNOUN + c], Wn[(size_t)(2 * dd + 1) * NNOUN + c]);
    }
    __syncthreads();

    const int w = tid >> 5, lane = tid & 31;
    for (int q = 0; q < 4; q++) {
        const int b = w * 4 + q;
        unsigned long long np[16];
        const unsigned long long* nb = (const unsigned long long*)(nsh + b * 32);
#pragma unroll
        for (int i = 0; i < 16; i++) np[i] = nb[i];

        // pass 1: max + first-index argmax
        float lm = -1e30f; int li = 1 << 30;
        for (int j = lane; j < MAXN; j += 32) {
            unsigned long long acc = 0ull;
#pragma unroll
            for (int i = 0; i < 16; i++) acc = ffma2(np[i], Wg8[i * 512 + j], acc);
            float lo, hi; unpack2(acc, lo, hi);
            float v = lo + hi + bg[j];
            if (v > lm) { lm = v; li = j; }   // ascending j -> strict > keeps first
        }
#pragma unroll
        for (int off = 16; off; off >>= 1) {
            float ov = __shfl_xor_sync(0xffffffffu, lm, off);
            int   oi = __shfl_xor_sync(0xffffffffu, li, off);
            if (ov > lm || (ov == lm && oi < li)) { lm = ov; li = oi; }
        }
        // pass 2: sum of exps (recompute dot)
        float ls = 0.f;
        for (int j = lane; j < MAXN; j += 32) {
            unsigned long long acc = 0ull;
#pragma unroll
            for (int i = 0; i < 16; i++) acc = ffma2(np[i], Wg8[i * 512 + j], acc);
            float lo, hi; unpack2(acc, lo, hi);
            ls += __expf(lo + hi + bg[j] - lm);
        }
#pragma unroll
        for (int off = 16; off; off >>= 1) ls += __shfl_xor_sync(0xffffffffu, ls, off);

        if (lane == 0) {
            int o = r * BATCH + b;
            g_rmax[o]  = lm;
            g_marg[o]  = lm + logf(ls);
            g_rmaxi[o] = sidx[li];
        }
    }
}

// ============================================================================
// K5: per-batch epilogue
// ============================================================================
__global__ __launch_bounds__(256) void final_kernel(
    const int* __restrict__ pad, float* __restrict__ out)
{
    const int b = blockIdx.x;
    __shared__ float mc[NROLE + 1];
    __shared__ float xc[NROLE + 1];
    __shared__ int   ic[NROLE + 1];
    __shared__ float vmarg[NVERB];
    __shared__ float red[256];
    const int tid = threadIdx.x;

    if (tid == 0) { mc[0] = 0.f; xc[0] = 0.f; ic[0] = 0; }
    for (int j = tid; j < NROLE; j += 256) {
        mc[j + 1] = g_marg[j * BATCH + b];
        xc[j + 1] = g_rmax[j * BATCH + b];
        ic[j + 1] = g_rmaxi[j * BATCH + b];
    }
    __syncthreads();

    const float* vpot = out + O_VPOT + (size_t)b * NVERB;
    for (int v = tid; v < NVERB; v += 256) {
        float sm = 0.f, sx = 0.f;
#pragma unroll
        for (int s = 0; s < MRMAX; s++) {
            int p = pad[v * MRMAX + s];
            sm += mc[p]; sx += xc[p];
            out[O_MAXI + ((size_t)b * NVERB + v) * MRMAX + s] = (float)ic[p];
        }
        float vp = vpot[v];
        vmarg[v] = sm + vp;
        out[O_VMAX + (size_t)b * NVERB + v] = sx + vp;
    }
    __syncthreads();

    float lm = -1e30f;
    for (int v = tid; v < NVERB; v += 256) lm = fmaxf(lm, vmarg[v]);
    red[tid] = lm; __syncthreads();
    for (int s = 128; s; s >>= 1) { if (tid < s) red[tid] = fmaxf(red[tid], red[tid + s]); __syncthreads(); }
    float gm = red[0]; __syncthreads();

    float ls = 0.f;
    for (int v = tid; v < NVERB; v += 256) ls += __expf(vmarg[v] - gm);
    red[tid] = ls; __syncthreads();
    for (int s = 128; s; s >>= 1) { if (tid < s) red[tid] += red[tid + s]; __syncthreads(); }
    if (tid == 0) out[O_NORM + b] = gm + logf(red[0]);
}

// ============================================================================
// launch
// ============================================================================
extern "C" void kernel_launch(void* const* d_in, const int* in_sizes, int n_in,
                              void* d_out, int out_size)
{
    const float* rep  = (const float*)d_in[0];
    const float* W_v  = (const float*)d_in[1];
    const float* b_v  = (const float*)d_in[2];
    const float* W_r  = (const float*)d_in[3];
    const float* b_r  = (const float*)d_in[4];
    const float* inw  = (const float*)d_in[5];
    const float* inb  = (const float*)d_in[6];
    const float* ow   = (const float*)d_in[7];
    const float* ob   = (const float*)d_in[8];
    const float* W_n  = (const float*)d_in[9];
    const float* b_n  = (const float*)d_in[10];
    const int*   ridx = (const int*)d_in[11];
    const int*   pad  = (const int*)d_in[12];
    float* out = (float*)d_out;

    static bool attr_set = false;
    if (!attr_set) {
        cudaFuncSetAttribute(group_kernel, cudaFuncAttributeMaxDynamicSharedMemorySize, 73728);
        attr_set = true;
    }

    // rep passthrough
    cudaMemcpyAsync(out + O_REP, rep, (size_t)BATCH * REPD * sizeof(float),
                    cudaMemcpyDeviceToDevice);

    // v_potential and node0
    gemm_rep_kernel<<<dim3(8, 2), 256>>>(rep, W_v, b_v, out + O_VPOT, NVERB, 0);
    gemm_rep_kernel<<<dim3(95, 2), 256>>>(rep, W_r, b_r, nullptr, NROLE * HIDE, 1);

    // 3 MHA layers (qkv fused into attn)
    for (int i = 0; i < 3; i++) {
        attn_kernel<<<dim3(NHEAD, BATCH), 192>>>(inw, inb, i);
        proj_kernel<<<760, 256>>>(ow, ob, i);
    }

    // grouped reductions (independent of rn buffer now)
    group_kernel<<<NROLE, 256, 73728>>>(W_n, b_n, ridx);

    // rn_potential (big GEMM) straight into the output buffer
    gemm_big_kernel<<<dim3(91, 48), 256>>>(W_n, b_n, out + O_RN);

    // final per-batch epilogue
    final_kernel<<<BATCH, 256>>>(pad, out);
}

// round 6
// speedup vs baseline: 1.2358x; 1.1411x over previous
#include <cuda_runtime.h>
#include <math.h>
#include <stdint.h>

typedef unsigned long long ull;

// ---------------- problem constants ----------------
#define BATCH   32
#define REPD    1024
#define NVERB   504
#define NROLE   190
#define NNOUN   11538
#define MRMAX   6
#define HIDE    32
#define NHEAD   4
#define HDIM    8
#define MAXN    512
#define ROWS    6080            // NROLE * BATCH

// output offsets (float32 concat of the returned tuple)
#define O_REP   0
#define O_VPOT  32768
#define O_RN    48896
#define O_NORM  70199936
#define O_VMAX  70199968
#define O_MAXI  70216096

// ---------------- scratch ----------------
__device__ float g_node[ROWS * HIDE];
__device__ float g_aoA[ROWS * HIDE];
__device__ float g_aoB[ROWS * HIDE];
__device__ float g_wnp[32 * NNOUN];   // Wn' = ow2^T @ Wn
__device__ float g_bnp[NNOUN];        // bn' = bn + ob2 @ Wn
__device__ float g_wc[2 * 96 * 32];   // combined qkv weights for layers 1,2
__device__ float g_bc[2 * 96];
__device__ float g_marg[ROWS];
__device__ float g_rmax[ROWS];
__device__ int   g_rmaxi[ROWS];

// ---------------- f32x2 helpers ----------------
__device__ __forceinline__ ull pack2(float lo, float hi) {
    ull r;
    asm("mov.b64 %0, {%1, %2};" : "=l"(r) : "r"(__float_as_uint(lo)), "r"(__float_as_uint(hi)));
    return r;
}
__device__ __forceinline__ void unpack2(ull p, float& lo, float& hi) {
    unsigned int a, b;
    asm("mov.b64 {%0, %1}, %2;" : "=r"(a), "=r"(b) : "l"(p));
    lo = __uint_as_float(a); hi = __uint_as_float(b);
}
__device__ __forceinline__ ull ffma2(ull a, ull b, ull c) {
    ull d;
    asm("fma.rn.f32x2 %0, %1, %2, %3;" : "=l"(d) : "l"(a), "l"(b), "l"(c));
    return d;
}

// ============================================================================
// prep: Wn' / bn'  (blocks 0..45) and combined layer weights WC/bC (block 46)
// ============================================================================
__global__ __launch_bounds__(256) void prep_kernel(
    const float* __restrict__ inw, const float* __restrict__ inb,
    const float* __restrict__ ow,  const float* __restrict__ ob,
    const float* __restrict__ Wn,  const float* __restrict__ bn)
{
    const int bx = blockIdx.x, tid = threadIdx.x;
    if (bx < 46) {
        __shared__ float ows[32][32];   // ow[2][e][d]
        __shared__ float obs[32];
#pragma unroll
        for (int it = 0; it < 4; it++) {
            int e2 = tid + it * 256;
            ows[e2 >> 5][e2 & 31] = ow[2 * 1024 + e2];
        }
        if (tid < 32) obs[tid] = ob[2 * 32 + tid];
        __syncthreads();
        int c = bx * 256 + tid;
        if (c < NNOUN) {
            float acc[32];
#pragma unroll
            for (int d = 0; d < 32; d++) acc[d] = 0.f;
            float bacc = 0.f;
#pragma unroll 4
            for (int e = 0; e < 32; e++) {
                float w = Wn[(size_t)e * NNOUN + c];
                bacc += obs[e] * w;
#pragma unroll
                for (int d = 0; d < 32; d++) acc[d] += ows[e][d] * w;
            }
#pragma unroll
            for (int d = 0; d < 32; d++) g_wnp[(size_t)d * NNOUN + c] = acc[d];
            g_bnp[c] = bn[c] + bacc;
        }
    } else {
        // WC[L][c][j] = sum_e inw[L+1][c][e] * ow[L][e][j]
        // bC[L][c]    = inb[L+1][c] + sum_e ob[L][e] * inw[L+1][c][e]
        if (tid < 192) {
            int L = tid / 96, c = tid % 96;
            float xr[32];
#pragma unroll
            for (int e = 0; e < 32; e++) xr[e] = inw[(size_t)(L + 1) * 96 * 32 + c * 32 + e];
            float bacc = 0.f;
#pragma unroll
            for (int e = 0; e < 32; e++) bacc += ob[L * 32 + e] * xr[e];
            g_bc[L * 96 + c] = inb[(L + 1) * 96 + c] + bacc;
            for (int j = 0; j < 32; j++) {
                float a = 0.f;
#pragma unroll
                for (int e = 0; e < 32; e++) a += xr[e] * ow[(size_t)L * 1024 + e * 32 + j];
                g_wc[(size_t)L * 3072 + c * 32 + j] = a;
            }
        }
    }
}

// ============================================================================
// combined rep GEMMs: blocks x<8 -> v_potential (N=504); x>=8 -> node (N=6080)
// ============================================================================
__global__ __launch_bounds__(256) void gemm_rep_kernel(
    const float* __restrict__ A,
    const float* __restrict__ W_v, const float* __restrict__ b_v,
    const float* __restrict__ W_r, const float* __restrict__ b_r,
    float* __restrict__ vpot)
{
    __shared__ float As[16][33];
    __shared__ float Bs[32][64];
    const int tid = threadIdx.x;
    const int tx = tid & 31, ty = tid >> 5;
    const bool verb = blockIdx.x < 8;
    const int n0 = (verb ? blockIdx.x : (blockIdx.x - 8)) * 64;
    const int m0 = blockIdx.y * 16;
    const int N = verb ? NVERB : (NROLE * HIDE);
    const float* Bm = verb ? W_v : W_r;
    const float* bias = verb ? b_v : b_r;

    float acc00 = 0.f, acc01 = 0.f, acc10 = 0.f, acc11 = 0.f;
    for (int k0 = 0; k0 < REPD; k0 += 32) {
        {
            int m = tid >> 4, kk = (tid & 15) * 2;
            float2 v = *(const float2*)(A + (m0 + m) * REPD + k0 + kk);
            As[m][kk] = v.x; As[m][kk + 1] = v.y;
        }
#pragma unroll
        for (int it = 0; it < 8; it++) {
            int idx = tid + it * 256;
            int kk = idx >> 6, cc = idx & 63;
            int col = n0 + cc;
            Bs[kk][cc] = (col < N) ? Bm[(size_t)(k0 + kk) * N + col] : 0.f;
        }
        __syncthreads();
#pragma unroll
        for (int kk = 0; kk < 32; kk++) {
            float a0 = As[ty * 2 + 0][kk];
            float a1 = As[ty * 2 + 1][kk];
            float b0 = Bs[kk][tx], b1 = Bs[kk][tx + 32];
            acc00 += a0 * b0; acc01 += a0 * b1;
            acc10 += a1 * b0; acc11 += a1 * b1;
        }
        __syncthreads();
    }
    float accs[2][2] = {{acc00, acc01}, {acc10, acc11}};
#pragma unroll
    for (int r = 0; r < 2; r++)
#pragma unroll
        for (int c = 0; c < 2; c++) {
            int row = m0 + ty * 2 + r;
            int col = n0 + tx + 32 * c;
            if (col < N) {
                float v = accs[r][c] + bias[col];
                if (verb) vpot[(size_t)row * NVERB + col] = v;
                else g_node[(size_t)(col >> 5) * (BATCH * HIDE) + row * HIDE + (col & 31)] = v;
            }
        }
}

// ============================================================================
// attn: fused qkv + two-pass softmax + AV for one (head, batch)
// wsel 0: weights = inw/inb (layer 0); wsel 1,2: combined g_wc/g_bc
// xsel 0: x=g_node -> g_aoA; 1: g_aoA -> g_aoB; 2: g_aoB -> g_aoA
// ============================================================================
__global__ __launch_bounds__(192) void attn_kernel(
    const float* __restrict__ inw, const float* __restrict__ inb, int wsel, int xsel)
{
    const int h = blockIdx.x, b = blockIdx.y;
    __shared__ __align__(16) float xs[NROLE][HIDE];
    __shared__ __align__(16) float ks[NROLE][HDIM];
    __shared__ __align__(16) float vs[NROLE][HDIM];
    __shared__ __align__(16) float wsh[24][HIDE];
    __shared__ float bsh[24];
    const int tid = threadIdx.x;

    const float* wbase = (wsel == 0) ? inw : (g_wc + (size_t)(wsel - 1) * 3072);
    const float* bbase = (wsel == 0) ? inb : (g_bc + (wsel - 1) * 96);
    const float* xsrc  = (xsel == 0) ? g_node : (xsel == 1 ? g_aoA : g_aoB);
    float* osrc        = (xsel == 1) ? g_aoB : g_aoA;

    for (int e = tid; e < NROLE * HIDE; e += 192) {
        int m = e >> 5, d = e & 31;
        xs[m][d] = xsrc[(size_t)(m * BATCH + b) * HIDE + d];
    }
    for (int e = tid; e < 24 * HIDE; e += 192) {
        int rr = e >> 5, d = e & 31;
        int grow = (rr >> 3) * HIDE + h * HDIM + (rr & 7);
        wsh[rr][d] = wbase[(size_t)grow * HIDE + d];
    }
    if (tid < 24) {
        int grow = (tid >> 3) * HIDE + h * HDIM + (tid & 7);
        bsh[tid] = bbase[grow];
    }
    __syncthreads();

    for (int o = tid; o < NROLE * 16; o += 192) {
        int m = o >> 4, c = o & 15;
        int wr = 8 + c;
        const ull* xp = (const ull*)xs[m];
        const ull* wp = (const ull*)wsh[wr];
        ull acc = 0ull;
#pragma unroll
        for (int i = 0; i < 16; i++) acc = ffma2(xp[i], wp[i], acc);
        float lo, hi; unpack2(acc, lo, hi);
        float val = lo + hi + bsh[wr];
        if (c < 8) ks[m][c] = val; else vs[m][c - 8] = val;
    }
    __syncthreads();

    const int l = tid;
    if (l < NROLE) {
        ull qp[4];
        {
            const ull* xp = (const ull*)xs[l];
            float qv[8];
#pragma unroll
            for (int d = 0; d < 8; d++) {
                const ull* wp = (const ull*)wsh[d];
                ull acc = 0ull;
#pragma unroll
                for (int i = 0; i < 16; i++) acc = ffma2(xp[i], wp[i], acc);
                float lo, hi; unpack2(acc, lo, hi);
                qv[d] = lo + hi + bsh[d];
            }
#pragma unroll
            for (int i = 0; i < 4; i++) qp[i] = pack2(qv[2 * i], qv[2 * i + 1]);
        }
        const float scale = 0.3535533905932738f;

        float mx = -1e30f;
        for (int m = 0; m < NROLE; m++) {
            const ull* kr = (const ull*)ks[m];
            ull acc = 0ull;
#pragma unroll
            for (int i = 0; i < 4; i++) acc = ffma2(qp[i], kr[i], acc);
            float lo, hi; unpack2(acc, lo, hi);
            mx = fmaxf(mx, (lo + hi) * scale);
        }
        float ssum = 0.f;
        ull racc[4] = {0ull, 0ull, 0ull, 0ull};
        for (int m = 0; m < NROLE; m++) {
            const ull* kr = (const ull*)ks[m];
            ull acc = 0ull;
#pragma unroll
            for (int i = 0; i < 4; i++) acc = ffma2(qp[i], kr[i], acc);
            float lo, hi; unpack2(acc, lo, hi);
            float p = __expf((lo + hi) * scale - mx);
            ssum += p;
            ull pp = pack2(p, p);
            const ull* vr = (const ull*)vs[m];
#pragma unroll
            for (int i = 0; i < 4; i++) racc[i] = ffma2(pp, vr[i], racc[i]);
        }
        float inv = 1.f / ssum;
        float* op = osrc + (size_t)(l * BATCH + b) * HIDE + h * HDIM;
        float4 o0, o1; float lo, hi;
        unpack2(racc[0], lo, hi); o0.x = lo * inv; o0.y = hi * inv;
        unpack2(racc[1], lo, hi); o0.z = lo * inv; o0.w = hi * inv;
        unpack2(racc[2], lo, hi); o1.x = lo * inv; o1.y = hi * inv;
        unpack2(racc[3], lo, hi); o1.z = lo * inv; o1.w = hi * inv;
        *(float4*)op = o0; *(float4*)(op + 4) = o1;
    }
}

// ============================================================================
// gemm_big: rn = ao2(6080x32) @ Wn'(32x11538) + bn'
// BM=64, BN=128, 256 threads, per-thread 4x8 (16 f32x2 accs).
// A pre-duplicated into smem as f32x2 pairs -> no per-k packing.
// ============================================================================
__global__ __launch_bounds__(256) void gemm_big_kernel(float* __restrict__ Crn)
{
    __shared__ ull   Ad[32 * 64];     // [k][m], dup-packed, 16KB
    __shared__ float Bs[32 * 128];    // 16KB
    __shared__ float bns[128];

    const int tid = threadIdx.x;
    const int tx = tid & 15, ty = tid >> 4;
    const int n0 = blockIdx.x * 128;
    const int m0 = blockIdx.y * 64;

#pragma unroll
    for (int it = 0; it < 2; it++) {
        int q = tid + it * 256;            // 0..511 float4 ids
        int r = q >> 3, k4 = (q & 7) * 4;
        float4 v = *(const float4*)(g_aoA + (size_t)(m0 + r) * HIDE + k4);
        Ad[(k4 + 0) * 64 + r] = pack2(v.x, v.x);
        Ad[(k4 + 1) * 64 + r] = pack2(v.y, v.y);
        Ad[(k4 + 2) * 64 + r] = pack2(v.z, v.z);
        Ad[(k4 + 3) * 64 + r] = pack2(v.w, v.w);
    }
#pragma unroll
    for (int it = 0; it < 8; it++) {
        int q = tid + it * 256;
        int kk = q >> 6, c2 = (q & 63) * 2;
        int col = n0 + c2;
        float2 v = make_float2(0.f, 0.f);
        if (col < NNOUN) v = *(const float2*)(g_wnp + (size_t)kk * NNOUN + col);
        *(float2*)&Bs[kk * 128 + c2] = v;
    }
    if (tid < 128) bns[tid] = (n0 + tid < NNOUN) ? g_bnp[n0 + tid] : 0.f;
    __syncthreads();

    ull acc[4][4];
#pragma unroll
    for (int i = 0; i < 4; i++)
#pragma unroll
        for (int j = 0; j < 4; j++) acc[i][j] = 0ull;

    for (int k = 0; k < 32; k++) {
        const ull* ad = Ad + k * 64 + ty * 4;
        ull a0 = ad[0], a1 = ad[1], a2 = ad[2], a3 = ad[3];
        const float* br = Bs + k * 128 + 2 * tx;
        ull b0 = *(const ull*)(br);
        ull b1 = *(const ull*)(br + 32);
        ull b2 = *(const ull*)(br + 64);
        ull b3 = *(const ull*)(br + 96);
        acc[0][0] = ffma2(a0, b0, acc[0][0]); acc[0][1] = ffma2(a0, b1, acc[0][1]);
        acc[0][2] = ffma2(a0, b2, acc[0][2]); acc[0][3] = ffma2(a0, b3, acc[0][3]);
        acc[1][0] = ffma2(a1, b0, acc[1][0]); acc[1][1] = ffma2(a1, b1, acc[1][1]);
        acc[1][2] = ffma2(a1, b2, acc[1][2]); acc[1][3] = ffma2(a1, b3, acc[1][3]);
        acc[2][0] = ffma2(a2, b0, acc[2][0]); acc[2][1] = ffma2(a2, b1, acc[2][1]);
        acc[2][2] = ffma2(a2, b2, acc[2][2]); acc[2][3] = ffma2(a2, b3, acc[2][3]);
        acc[3][0] = ffma2(a3, b0, acc[3][0]); acc[3][1] = ffma2(a3, b1, acc[3][1]);
        acc[3][2] = ffma2(a3, b2, acc[3][2]); acc[3][3] = ffma2(a3, b3, acc[3][3]);
    }

#pragma unroll
    for (int i = 0; i < 4; i++) {
        int m = m0 + ty * 4 + i;
        float* crow = Crn + (size_t)m * NNOUN;
#pragma unroll
        for (int j = 0; j < 4; j++) {
            int col = n0 + 2 * tx + 32 * j;
            if (col < NNOUN) {
                float lo, hi; unpack2(acc[i][j], lo, hi);
                float2 bb = *(const float2*)&bns[2 * tx + 32 * j];
                *(float2*)(crow + col) = make_float2(lo + bb.x, hi + bb.y);
            }
        }
    }
}

// ============================================================================
// group: grouped max / first-argmax / logsumexp per (role, batch), recomputed
// from ao2 @ gathered Wn' columns. one block per role, 72KB dynamic smem.
// ============================================================================
__global__ __launch_bounds__(256) void group_kernel(const int* __restrict__ rnidx)
{
    extern __shared__ __align__(16) float gsm[];
    ull*   Wg8  = (ull*)gsm;              // [16][512] f32x2 pairs (64KB)
    float* nsh  = gsm + 16384;            // [32][32] ao rows
    float* bg   = gsm + 17408;            // [512]
    int*   sidx = (int*)(gsm + 17920);    // [512]
    const int r = blockIdx.x, tid = threadIdx.x;

    sidx[tid]       = rnidx[(size_t)r * MAXN + tid];
    sidx[tid + 256] = rnidx[(size_t)r * MAXN + tid + 256];
    for (int e = tid; e < 1024; e += 256) nsh[e] = g_aoA[(size_t)r * 1024 + e];
    __syncthreads();
    for (int e = tid; e < 512; e += 256) bg[e] = g_bnp[sidx[e]];
    for (int e = tid; e < 8192; e += 256) {
        int dd = e >> 9, j = e & 511;
        int c = sidx[j];
        Wg8[e] = pack2(g_wnp[(size_t)(2 * dd) * NNOUN + c],
                       g_wnp[(size_t)(2 * dd + 1) * NNOUN + c]);
    }
    __syncthreads();

    const int w = tid >> 5, lane = tid & 31;
    for (int q = 0; q < 4; q++) {
        const int b = w * 4 + q;
        ull np[16];
        const ull* nb = (const ull*)(nsh + b * 32);
#pragma unroll
        for (int i = 0; i < 16; i++) np[i] = nb[i];

        float lm = -1e30f; int li = 1 << 30;
        for (int j = lane; j < MAXN; j += 32) {
            ull acc = 0ull;
#pragma unroll
            for (int i = 0; i < 16; i++) acc = ffma2(np[i], Wg8[i * 512 + j], acc);
            float lo, hi; unpack2(acc, lo, hi);
            float v = lo + hi + bg[j];
            if (v > lm) { lm = v; li = j; }
        }
#pragma unroll
        for (int off = 16; off; off >>= 1) {
            float ov = __shfl_xor_sync(0xffffffffu, lm, off);
            int   oi = __shfl_xor_sync(0xffffffffu, li, off);
            if (ov > lm || (ov == lm && oi < li)) { lm = ov; li = oi; }
        }
        float ls = 0.f;
        for (int j = lane; j < MAXN; j += 32) {
            ull acc = 0ull;
#pragma unroll
            for (int i = 0; i < 16; i++) acc = ffma2(np[i], Wg8[i * 512 + j], acc);
            float lo, hi; unpack2(acc, lo, hi);
            ls += __expf(lo + hi + bg[j] - lm);
        }
#pragma unroll
        for (int off = 16; off; off >>= 1) ls += __shfl_xor_sync(0xffffffffu, ls, off);

        if (lane == 0) {
            int o = r * BATCH + b;
            g_rmax[o]  = lm;
            g_marg[o]  = lm + logf(ls);
            g_rmaxi[o] = sidx[li];
        }
    }
}

// ============================================================================
// final per-batch epilogue
// ============================================================================
__global__ __launch_bounds__(256) void final_kernel(
    const int* __restrict__ pad, float* __restrict__ out)
{
    const int b = blockIdx.x;
    __shared__ float mc[NROLE + 1];
    __shared__ float xc[NROLE + 1];
    __shared__ int   ic[NROLE + 1];
    __shared__ float vmarg[NVERB];
    __shared__ float red[256];
    const int tid = threadIdx.x;

    if (tid == 0) { mc[0] = 0.f; xc[0] = 0.f; ic[0] = 0; }
    for (int j = tid; j < NROLE; j += 256) {
        mc[j + 1] = g_marg[j * BATCH + b];
        xc[j + 1] = g_rmax[j * BATCH + b];
        ic[j + 1] = g_rmaxi[j * BATCH + b];
    }
    __syncthreads();

    const float* vpot = out + O_VPOT + (size_t)b * NVERB;
    for (int v = tid; v < NVERB; v += 256) {
        float sm = 0.f, sx = 0.f;
#pragma unroll
        for (int s = 0; s < MRMAX; s++) {
            int p = pad[v * MRMAX + s];
            sm += mc[p]; sx += xc[p];
            out[O_MAXI + ((size_t)b * NVERB + v) * MRMAX + s] = (float)ic[p];
        }
        float vp = vpot[v];
        vmarg[v] = sm + vp;
        out[O_VMAX + (size_t)b * NVERB + v] = sx + vp;
    }
    __syncthreads();

    float lm = -1e30f;
    for (int v = tid; v < NVERB; v += 256) lm = fmaxf(lm, vmarg[v]);
    red[tid] = lm; __syncthreads();
    for (int s = 128; s; s >>= 1) { if (tid < s) red[tid] = fmaxf(red[tid], red[tid + s]); __syncthreads(); }
    float gm = red[0]; __syncthreads();

    float ls = 0.f;
    for (int v = tid; v < NVERB; v += 256) ls += __expf(vmarg[v] - gm);
    red[tid] = ls; __syncthreads();
    for (int s = 128; s; s >>= 1) { if (tid < s) red[tid] += red[tid + s]; __syncthreads(); }
    if (tid == 0) out[O_NORM + b] = gm + logf(red[0]);
}

// ============================================================================
// launch — kernel order chosen so gemm_big is the 6th kernel (ncu -s 5 -c 1)
// ============================================================================
extern "C" void kernel_launch(void* const* d_in, const int* in_sizes, int n_in,
                              void* d_out, int out_size)
{
    const float* rep  = (const float*)d_in[0];
    const float* W_v  = (const float*)d_in[1];
    const float* b_v  = (const float*)d_in[2];
    const float* W_r  = (const float*)d_in[3];
    const float* b_r  = (const float*)d_in[4];
    const float* inw  = (const float*)d_in[5];
    const float* inb  = (const float*)d_in[6];
    const float* ow   = (const float*)d_in[7];
    const float* ob   = (const float*)d_in[8];
    const float* W_n  = (const float*)d_in[9];
    const float* b_n  = (const float*)d_in[10];
    const int*   ridx = (const int*)d_in[11];
    const int*   pad  = (const int*)d_in[12];
    float* out = (float*)d_out;

    static bool attr_set = false;
    if (!attr_set) {
        cudaFuncSetAttribute(group_kernel, cudaFuncAttributeMaxDynamicSharedMemorySize, 73728);
        attr_set = true;
    }

    // 1: weight pre-folding (Wn', bn', WC, bC)
    prep_kernel<<<47, 256>>>(inw, inb, ow, ob, W_n, b_n);
    // 2: v_potential + node0
    gemm_rep_kernel<<<dim3(103, 2), 256>>>(rep, W_v, b_v, W_r, b_r, out + O_VPOT);
    // 3-5: three MHA layers (proj folded into next layer's weights)
    attn_kernel<<<dim3(NHEAD, BATCH), 192>>>(inw, inb, 0, 0);
    attn_kernel<<<dim3(NHEAD, BATCH), 192>>>(inw, inb, 1, 1);
    attn_kernel<<<dim3(NHEAD, BATCH), 192>>>(inw, inb, 2, 2);
    // 6: rn_potential (the big one — now profiled by ncu)
    gemm_big_kernel<<<dim3(91, 95), 256>>>(out + O_RN);
    // 7: grouped reductions
    group_kernel<<<NROLE, 256, 73728>>>(ridx);
    // 8: per-batch epilogue
    final_kernel<<<BATCH, 256>>>(pad, out);
    // rep passthrough (copy engine; kept last so kernel ordering is stable)
    cudaMemcpyAsync(out + O_REP, rep, (size_t)BATCH * REPD * sizeof(float),
                    cudaMemcpyDeviceToDevice);
}